// round 15
// baseline (speedup 1.0000x reference)
#include <cuda_runtime.h>
#include <cstdint>

#define Cc 64
#define CO 64
#define Ss 256
#define LL (Ss * Ss)

#define CHUNK 8                  // channels per stage
#define NCHUNK (Cc / CHUNK)      // 8 stages
#define ROWB 576                 // bytes per staged w row (144 floats)
#define ROWF 144
#define W_ROWS 72                // CHUNK*9
#define X_OFF_B 41472            // W_ROWS*ROWB
#define STAGE_B 45568            // + CHUNK*512 (x rows)
#define STAGE_F (STAGE_B / 4)

// ---------------------------------------------------------------------------
// Depth-2 bulk-copy pipelined fused Reverb kernel.
//   g[c,l]   = x[c,l] * sum_{i,j valid} w[c*9+i*3+j, (y+1-i)*S + (x+1-j)]
//   out[o,l] = sum_c conv[c,o] * g[c,l]
// Block owns 128 px. A 2-slot smem ring holds RAW w rows (144 floats, widened
// so edge taps are in-slot) + x, filled by cp.async.bulk TWO chunks ahead
// (issued by warp 0, ~3 copies/lane, zero register staging). Per chunk:
// mbar-wait -> g-compute from raw smem -> sync -> issue bulk(s+2) -> mix.
// ---------------------------------------------------------------------------
__global__ __launch_bounds__(256) void reverb_bulk_kernel(
    const float* __restrict__ x,      // (C, L)
    const float* __restrict__ w,      // (C*9, L)
    const float* __restrict__ conv,   // (C, CO)
    float* __restrict__ out)          // (CO, L)
{
    extern __shared__ __align__(16) float raw[];          // 2 * STAGE_F floats
    __shared__ __align__(16) float sconv[Cc * CO];        // 16 KB
    __shared__ __align__(16) float sg[CHUNK * 128];       // 4 KB
    __shared__ __align__(8) unsigned long long mbars[2];

    const int tid = threadIdx.x;
    const int wid = tid >> 5;
    const int lane = tid & 31;

#pragma unroll
    for (int k = 0; k < 4; k++) {
        const int i = tid + 256 * k;
        ((float4*)sconv)[i] = ((const float4*)conv)[i];
    }

    const int lbase = blockIdx.x * 128;
    const int yb = lbase >> 8;
    const int xb = lbase & 255;           // 0 or 128
    const int S0 = (xb == 0) ? 0 : xb - 16;   // staged segment start col
    const int xofs = (xb == 0) ? 0 : 16;

    // y-clamped row offsets + masks
    float my[3];
    int rowY[3];
#pragma unroll
    for (int i = 0; i < 3; i++) {
        const int ry = yb + 1 - i;
        const bool vy = (unsigned)ry < (unsigned)Ss;
        my[i] = vy ? 1.0f : 0.0f;
        rowY[i] = (vy ? ry : yb) * Ss;
    }

    const uint32_t raw_u32 = (uint32_t)__cvta_generic_to_shared(raw);
    const uint32_t mbar_u32 = (uint32_t)__cvta_generic_to_shared(mbars);

    // ---- per-lane bulk-copy descriptors (3 slots, warp 0 only uses them) ----
    const float* cp_src[3];
    size_t cp_strd[3];
    uint32_t cp_dst[3];
    int cp_byt[3];
#pragma unroll
    for (int k = 0; k < 3; k++) {
        const int idx = lane + 32 * k;
        if (idx < W_ROWS) {
            const int p = idx % 9;
            const int i = p / 3;
            cp_src[k] = w + (size_t)idx * LL + rowY[i] + S0;
            cp_strd[k] = (size_t)W_ROWS * LL;
            cp_dst[k] = (uint32_t)(idx * ROWB);
            cp_byt[k] = ROWB;
        } else if (idx < 80) {
            const int c = idx - W_ROWS;
            cp_src[k] = x + (size_t)c * LL + lbase;
            cp_strd[k] = (size_t)CHUNK * LL;
            cp_dst[k] = (uint32_t)(X_OFF_B + c * 512);
            cp_byt[k] = 512;
        } else {
            cp_byt[k] = 0;
        }
    }

    auto ISSUE = [&](int s) {   // warp 0 only; fills slot s&1 with chunk s
        const uint32_t slot = raw_u32 + (uint32_t)((s & 1) * STAGE_B);
        const uint32_t mb = mbar_u32 + (uint32_t)((s & 1) * 8);
        if (lane == 0) {
            asm volatile("mbarrier.arrive.expect_tx.shared.b64 _, [%0], %1;"
                         :: "r"(mb), "r"((uint32_t)STAGE_B) : "memory");
        }
#pragma unroll
        for (int k = 0; k < 3; k++) {
            if (cp_byt[k] > 0) {
                asm volatile(
                    "cp.async.bulk.shared::cluster.global.mbarrier::complete_tx::bytes "
                    "[%0], [%1], %2, [%3];"
                    :: "r"(slot + cp_dst[k]), "l"(cp_src[k] + (size_t)s * cp_strd[k]),
                       "r"((uint32_t)cp_byt[k]), "r"(mb) : "memory");
            }
        }
    };

    // ---- init mbarriers, issue first two stages ----
    if (tid == 0) {
        asm volatile("mbarrier.init.shared.b64 [%0], 1;" :: "r"(mbar_u32) : "memory");
        asm volatile("mbarrier.init.shared.b64 [%0], 1;" :: "r"(mbar_u32 + 8) : "memory");
    }
    __syncthreads();
    if (wid == 0) { ISSUE(0); ISSUE(1); }

    // ---- task geometry for g-compute ----
    const int cl = wid;               // channel slot 0..7
    const int grp = lane;             // 4-px group 0..31
    const int x0 = xb + grp * 4;
    const int bx = grp * 4 + xofs;    // local col of px0 within 144-wide row
    const float mL = (x0 == 0) ? 0.0f : 1.0f;
    const float mR = (x0 == Ss - 4) ? 0.0f : 1.0f;
    const int bxL = (x0 == 0) ? bx : bx - 1;        // clamped (masked anyway)
    const int bxR = (x0 == Ss - 4) ? bx : bx + 4;

    unsigned long long acc[4][4];
#pragma unroll
    for (int op = 0; op < 4; op++)
#pragma unroll
        for (int p = 0; p < 4; p++) acc[op][p] = 0ull;

    const int og = wid;

    for (int s = 0; s < NCHUNK; s++) {
        __syncthreads();   // prev mix done with sg; prev raw reads done

        // wait for stage s (slot s&1, phase (s>>1)&1)
        {
            const uint32_t mb = mbar_u32 + (uint32_t)((s & 1) * 8);
            const uint32_t ph = (uint32_t)((s >> 1) & 1);
            uint32_t done;
            asm volatile(
                "{\n\t.reg .pred p;\n\t"
                "mbarrier.try_wait.parity.shared.b64 p, [%1], %2;\n\t"
                "selp.b32 %0, 1, 0, p;\n\t}"
                : "=r"(done) : "r"(mb), "r"(ph) : "memory");
            if (!done) {
                asm volatile(
                    "{\n\t.reg .pred p;\n\t"
                    "WL_%=:\n\t"
                    "mbarrier.try_wait.parity.shared.b64 p, [%0], %1;\n\t"
                    "@p bra.uni WD_%=;\n\t"
                    "bra.uni WL_%=;\n\t"
                    "WD_%=:\n\t}"
                    :: "r"(mb), "r"(ph) : "memory");
            }
        }

        // ---- g-compute from raw smem ----
        {
            const float* slot = raw + (s & 1) * STAGE_F;
            const float* base = slot + (cl * 9) * ROWF;
            float ws0 = 0.f, ws1 = 0.f, ws2 = 0.f, ws3 = 0.f;
#pragma unroll
            for (int i = 0; i < 3; i++) {
                const float* r0 = base + (3 * i) * ROWF;
                const float* r1 = r0 + ROWF;
                const float* r2 = r1 + ROWF;
                const float4 a = *(const float4*)(r0 + bx);
                const float4 b = *(const float4*)(r1 + bx);
                const float4 d = *(const float4*)(r2 + bx);
                const float lsv = mL * r2[bxL];
                const float rsv = mR * r0[bxR];
                ws0 = fmaf(my[i], (a.y + b.x) + lsv, ws0);
                ws1 = fmaf(my[i], (a.z + b.y) + d.x, ws1);
                ws2 = fmaf(my[i], (a.w + b.z) + d.y, ws2);
                ws3 = fmaf(my[i], (rsv + b.w) + d.z, ws3);
            }
            const float4 xv = *(const float4*)(slot + X_OFF_B / 4 + cl * 128 + grp * 4);
            float4 gv;
            gv.x = xv.x * ws0;
            gv.y = xv.y * ws1;
            gv.z = xv.z * ws2;
            gv.w = xv.w * ws3;
            *(float4*)(sg + cl * 128 + grp * 4) = gv;
        }

        __syncthreads();   // sg ready AND raw slot s&1 fully consumed

        if (wid == 0 && s + 2 < NCHUNK) ISSUE(s + 2);   // refill slot s&1

        // ---- mix chunk s from sg ----
#pragma unroll
        for (int c2 = 0; c2 < CHUNK; c2++) {
            const int c = s * CHUNK + c2;
            const float4 g4 = *(const float4*)(sg + c2 * 128 + lane * 4);
            unsigned long long gp[4];
            asm("mov.b64 %0, {%1, %1};" : "=l"(gp[0]) : "f"(g4.x));
            asm("mov.b64 %0, {%1, %1};" : "=l"(gp[1]) : "f"(g4.y));
            asm("mov.b64 %0, {%1, %1};" : "=l"(gp[2]) : "f"(g4.z));
            asm("mov.b64 %0, {%1, %1};" : "=l"(gp[3]) : "f"(g4.w));

            const ulonglong2* cv = (const ulonglong2*)(sconv + c * CO + og * 8);
            const ulonglong2 cva = cv[0];
            const ulonglong2 cvb = cv[1];
#pragma unroll
            for (int p = 0; p < 4; p++) {
                asm("fma.rn.f32x2 %0, %1, %2, %0;" : "+l"(acc[0][p]) : "l"(cva.x), "l"(gp[p]));
                asm("fma.rn.f32x2 %0, %1, %2, %0;" : "+l"(acc[1][p]) : "l"(cva.y), "l"(gp[p]));
                asm("fma.rn.f32x2 %0, %1, %2, %0;" : "+l"(acc[2][p]) : "l"(cvb.x), "l"(gp[p]));
                asm("fma.rn.f32x2 %0, %1, %2, %0;" : "+l"(acc[3][p]) : "l"(cvb.y), "l"(gp[p]));
            }
        }
    }

    // ---- Epilogue: unpack, 8 coalesced STG.128 per warp ----
#pragma unroll
    for (int op = 0; op < 4; op++) {
        unsigned int lo[4], hi[4];
#pragma unroll
        for (int p = 0; p < 4; p++) {
            asm("mov.b64 {%0, %1}, %2;" : "=r"(lo[p]), "=r"(hi[p]) : "l"(acc[op][p]));
        }
        const int o = og * 8 + 2 * op;
        float4 v0, v1;
        v0.x = __uint_as_float(lo[0]); v0.y = __uint_as_float(lo[1]);
        v0.z = __uint_as_float(lo[2]); v0.w = __uint_as_float(lo[3]);
        v1.x = __uint_as_float(hi[0]); v1.y = __uint_as_float(hi[1]);
        v1.z = __uint_as_float(hi[2]); v1.w = __uint_as_float(hi[3]);
        *(float4*)(out + (size_t)o * LL + lbase + lane * 4) = v0;
        *(float4*)(out + (size_t)(o + 1) * LL + lbase + lane * 4) = v1;
    }
}

extern "C" void kernel_launch(void* const* d_in, const int* in_sizes, int n_in,
                              void* d_out, int out_size) {
    const float* x    = (const float*)d_in[0];  // (1, C, S, S)
    const float* w    = (const float*)d_in[1];  // (1, C*9, L)
    const float* conv = (const float*)d_in[2];  // (C, CO)
    float* out = (float*)d_out;                 // (1, CO, S, S)

    const int dyn = 2 * STAGE_B;                // 91136 B raw ring
    cudaFuncSetAttribute(reverb_bulk_kernel,
                         cudaFuncAttributeMaxDynamicSharedMemorySize, dyn);
    reverb_bulk_kernel<<<LL / 128, 256, dyn>>>(x, w, conv, out);
}

// round 16
// speedup vs baseline: 1.5740x; 1.5740x over previous
#include <cuda_runtime.h>
#include <cuda.h>
#include <cstdint>
#include <dlfcn.h>

#define Cc 64
#define CO 64
#define Ss 256
#define LL (Ss * Ss)

#define CHUNK 8                  // channels per stage
#define NCHUNK (Cc / CHUNK)      // 8 stages
#define ROWF 144                 // staged w row: 144 floats (576 B)
#define ROWB 576
#define I_BLK_B 13824            // one i-slab: 8c * 3j * 576 B
#define X_OFF_B 41472            // 3 * I_BLK_B
#define STAGE_B 45568            // + 8 * 512 (x rows)
#define STAGE_F (STAGE_B / 4)

// ===========================================================================
// TMA-pipelined fused Reverb kernel.
//   g[c,l]   = x[c,l] * sum_{i,j valid} w[c*9+i*3+j, (y+1-i)*S + (x+1-j)]
//   out[o,l] = sum_c conv[c,o] * g[c,l]
// Block owns 128 px. 2-slot smem ring of raw w slabs (+x), filled TWO chunks
// ahead by 4 big TMA tensor loads per chunk (w viewed as 5D [x,y,j,i,c]).
// Per chunk: mbar-wait -> g-compute from raw smem -> sync -> issue(s+2) ->
// register-tiled mix.
// ===========================================================================
__global__ __launch_bounds__(256) void reverb_tma_kernel(
    const __grid_constant__ CUtensorMap wmap,
    const __grid_constant__ CUtensorMap xmap,
    const float* __restrict__ conv,   // (C, CO)
    float* __restrict__ out)          // (CO, L)
{
    extern __shared__ __align__(16) float raw[];          // 2 * STAGE_F
    __shared__ __align__(16) float sconv[Cc * CO];        // 16 KB
    __shared__ __align__(16) float sg[CHUNK * 128];       // 4 KB
    __shared__ __align__(8) unsigned long long mbars[2];

    const int tid = threadIdx.x;
    const int wid = tid >> 5;
    const int lane = tid & 31;

#pragma unroll
    for (int k = 0; k < 4; k++) {
        const int i = tid + 256 * k;
        ((float4*)sconv)[i] = ((const float4*)conv)[i];
    }

    const int lbase = blockIdx.x * 128;
    const int yb = lbase >> 8;
    const int xb = lbase & 255;               // 0 or 128
    const int S0 = (xb == 0) ? 0 : xb - 16;   // staged col start
    const int xofs = (xb == 0) ? 0 : 16;

    float my[3];
    int rowR[3];
#pragma unroll
    for (int i = 0; i < 3; i++) {
        const int ry = yb + 1 - i;
        const bool vy = (unsigned)ry < (unsigned)Ss;
        my[i] = vy ? 1.0f : 0.0f;
        rowR[i] = vy ? ry : yb;               // clamped row index
    }

    const uint32_t raw_u32 = (uint32_t)__cvta_generic_to_shared(raw);
    const uint32_t mbar_u32 = (uint32_t)__cvta_generic_to_shared(mbars);

    auto ISSUE = [&](int s) {   // tid==0 only: fill slot s&1 with chunk s
        const uint32_t slot = raw_u32 + (uint32_t)((s & 1) * STAGE_B);
        const uint32_t mb = mbar_u32 + (uint32_t)((s & 1) * 8);
        asm volatile("mbarrier.arrive.expect_tx.shared.b64 _, [%0], %1;"
                     :: "r"(mb), "r"((uint32_t)STAGE_B) : "memory");
#pragma unroll
        for (int i = 0; i < 3; i++) {
            asm volatile(
                "cp.async.bulk.tensor.5d.shared::cta.global.tile.mbarrier::complete_tx::bytes "
                "[%0], [%1, {%2, %3, %4, %5, %6}], [%7];"
                :: "r"(slot + (uint32_t)(i * I_BLK_B)), "l"(&wmap),
                   "r"(S0), "r"(rowR[i]), "r"(0), "r"(i), "r"(s * CHUNK),
                   "r"(mb) : "memory");
        }
        asm volatile(
            "cp.async.bulk.tensor.3d.shared::cta.global.tile.mbarrier::complete_tx::bytes "
            "[%0], [%1, {%2, %3, %4}], [%5];"
            :: "r"(slot + (uint32_t)X_OFF_B), "l"(&xmap),
               "r"(xb), "r"(yb), "r"(s * CHUNK), "r"(mb) : "memory");
    };

    if (tid == 0) {
        asm volatile("mbarrier.init.shared.b64 [%0], 1;" :: "r"(mbar_u32) : "memory");
        asm volatile("mbarrier.init.shared.b64 [%0], 1;" :: "r"(mbar_u32 + 8) : "memory");
        asm volatile("fence.proxy.async.shared::cta;" ::: "memory");
    }
    __syncthreads();
    if (tid == 0) { ISSUE(0); ISSUE(1); }

    // ---- task geometry for g-compute ----
    const int cl = wid;               // channel slot 0..7
    const int grp = lane;             // 4-px group
    const int x0 = xb + grp * 4;
    const int bx = grp * 4 + xofs;    // local col of px0 in 144-wide row
    const float mL = (x0 == 0) ? 0.0f : 1.0f;
    const float mR = (x0 == Ss - 4) ? 0.0f : 1.0f;
    const int bxL = (x0 == 0) ? bx : bx - 1;
    const int bxR = (x0 == Ss - 4) ? bx : bx + 4;

    unsigned long long acc[4][4];
#pragma unroll
    for (int op = 0; op < 4; op++)
#pragma unroll
        for (int p = 0; p < 4; p++) acc[op][p] = 0ull;

    const int og = wid;

    for (int s = 0; s < NCHUNK; s++) {
        __syncthreads();   // prev mix done reading sg; slot reads done

        // wait for stage s (slot s&1, phase (s>>1)&1)
        {
            const uint32_t mb = mbar_u32 + (uint32_t)((s & 1) * 8);
            const uint32_t ph = (uint32_t)((s >> 1) & 1);
            uint32_t done;
            asm volatile(
                "{\n\t.reg .pred p;\n\t"
                "mbarrier.try_wait.parity.shared.b64 p, [%1], %2;\n\t"
                "selp.b32 %0, 1, 0, p;\n\t}"
                : "=r"(done) : "r"(mb), "r"(ph) : "memory");
            if (!done) {
                asm volatile(
                    "{\n\t.reg .pred p;\n\t"
                    "WL_%=:\n\t"
                    "mbarrier.try_wait.parity.shared.b64 p, [%0], %1;\n\t"
                    "@p bra.uni WD_%=;\n\t"
                    "bra.uni WL_%=;\n\t"
                    "WD_%=:\n\t}"
                    :: "r"(mb), "r"(ph) : "memory");
            }
        }

        // ---- g-compute from raw smem: row(i,c,j) = i*3456 + c*432 + j*144 ----
        {
            const float* slot = raw + (s & 1) * STAGE_F;
            float ws0 = 0.f, ws1 = 0.f, ws2 = 0.f, ws3 = 0.f;
#pragma unroll
            for (int i = 0; i < 3; i++) {
                const float* r0 = slot + i * 3456 + cl * 432;
                const float* r1 = r0 + ROWF;
                const float* r2 = r1 + ROWF;
                const float4 a = *(const float4*)(r0 + bx);
                const float4 b = *(const float4*)(r1 + bx);
                const float4 d = *(const float4*)(r2 + bx);
                const float lsv = mL * r2[bxL];
                const float rsv = mR * r0[bxR];
                ws0 = fmaf(my[i], (a.y + b.x) + lsv, ws0);
                ws1 = fmaf(my[i], (a.z + b.y) + d.x, ws1);
                ws2 = fmaf(my[i], (a.w + b.z) + d.y, ws2);
                ws3 = fmaf(my[i], (rsv + b.w) + d.z, ws3);
            }
            const float4 xv = *(const float4*)(slot + X_OFF_B / 4 + cl * 128 + grp * 4);
            float4 gv;
            gv.x = xv.x * ws0;
            gv.y = xv.y * ws1;
            gv.z = xv.z * ws2;
            gv.w = xv.w * ws3;
            *(float4*)(sg + cl * 128 + grp * 4) = gv;
        }

        __syncthreads();   // sg ready AND slot fully consumed

        if (tid == 0 && s + 2 < NCHUNK) ISSUE(s + 2);

        // ---- mix chunk s from sg ----
#pragma unroll
        for (int c2 = 0; c2 < CHUNK; c2++) {
            const int c = s * CHUNK + c2;
            const float4 g4 = *(const float4*)(sg + c2 * 128 + lane * 4);
            unsigned long long gp[4];
            asm("mov.b64 %0, {%1, %1};" : "=l"(gp[0]) : "f"(g4.x));
            asm("mov.b64 %0, {%1, %1};" : "=l"(gp[1]) : "f"(g4.y));
            asm("mov.b64 %0, {%1, %1};" : "=l"(gp[2]) : "f"(g4.z));
            asm("mov.b64 %0, {%1, %1};" : "=l"(gp[3]) : "f"(g4.w));

            const ulonglong2* cv = (const ulonglong2*)(sconv + c * CO + og * 8);
            const ulonglong2 cva = cv[0];
            const ulonglong2 cvb = cv[1];
#pragma unroll
            for (int p = 0; p < 4; p++) {
                asm("fma.rn.f32x2 %0, %1, %2, %0;" : "+l"(acc[0][p]) : "l"(cva.x), "l"(gp[p]));
                asm("fma.rn.f32x2 %0, %1, %2, %0;" : "+l"(acc[1][p]) : "l"(cva.y), "l"(gp[p]));
                asm("fma.rn.f32x2 %0, %1, %2, %0;" : "+l"(acc[2][p]) : "l"(cvb.x), "l"(gp[p]));
                asm("fma.rn.f32x2 %0, %1, %2, %0;" : "+l"(acc[3][p]) : "l"(cvb.y), "l"(gp[p]));
            }
        }
    }

    // ---- Epilogue ----
#pragma unroll
    for (int op = 0; op < 4; op++) {
        unsigned int lo[4], hi[4];
#pragma unroll
        for (int p = 0; p < 4; p++) {
            asm("mov.b64 {%0, %1}, %2;" : "=r"(lo[p]), "=r"(hi[p]) : "l"(acc[op][p]));
        }
        const int o = og * 8 + 2 * op;
        float4 v0, v1;
        v0.x = __uint_as_float(lo[0]); v0.y = __uint_as_float(lo[1]);
        v0.z = __uint_as_float(lo[2]); v0.w = __uint_as_float(lo[3]);
        v1.x = __uint_as_float(hi[0]); v1.y = __uint_as_float(hi[1]);
        v1.z = __uint_as_float(hi[2]); v1.w = __uint_as_float(hi[3]);
        *(float4*)(out + (size_t)o * LL + lbase + lane * 4) = v0;
        *(float4*)(out + (size_t)(o + 1) * LL + lbase + lane * 4) = v1;
    }
}

// ===========================================================================
// Fallback: round-14 champion (register-staged LDG pipeline), used if the
// tensor-map encoder can't be resolved.
// ===========================================================================
__global__ __launch_bounds__(256, 2) void reverb_pipe_kernel(
    const float* __restrict__ x, const float* __restrict__ w,
    const float* __restrict__ conv, float* __restrict__ out)
{
    __shared__ __align__(16) float sconv[Cc * CO];
    __shared__ __align__(16) float sg[2][CHUNK * 128];

    const int tid = threadIdx.x;
    const int wid = tid >> 5;
    const int lane = tid & 31;

#pragma unroll
    for (int k = 0; k < 4; k++) {
        const int i = tid + 256 * k;
        ((float4*)sconv)[i] = ((const float4*)conv)[i];
    }

    const int lbase = blockIdx.x * 128;
    const int yb = lbase >> 8;
    const int xb = lbase & 255;
    const int cl = wid, grp = lane;
    const int x0 = xb + grp * 4;
    const bool edgeL = (lane == 0) && (x0 != 0);
    const bool edgeR = (lane == 31) && (x0 != Ss - 4);

    float my[3]; int rowoff[3];
#pragma unroll
    for (int i = 0; i < 3; i++) {
        const int ry = yb + 1 - i;
        const bool vy = (unsigned)ry < (unsigned)Ss;
        my[i] = vy ? 1.0f : 0.0f;
        rowoff[i] = (vy ? ry : yb) * Ss + x0;
    }

    float4 a[3], b[3], d[3], xv;
    float le[3], re[3];
    auto LOAD = [&](int s) {
        const int c = s * CHUNK + cl;
        const float* wc = w + (size_t)c * 9 * LL;
#pragma unroll
        for (int i = 0; i < 3; i++) {
            const float* p0 = wc + (size_t)(i * 3 + 0) * LL + rowoff[i];
            const float* p1 = wc + (size_t)(i * 3 + 1) * LL + rowoff[i];
            const float* p2 = wc + (size_t)(i * 3 + 2) * LL + rowoff[i];
            a[i] = __ldg((const float4*)p0);
            b[i] = __ldg((const float4*)p1);
            d[i] = __ldg((const float4*)p2);
            le[i] = edgeL ? __ldg(p2 - 1) : 0.0f;
            re[i] = edgeR ? __ldg(p0 + 4) : 0.0f;
        }
        xv = __ldg((const float4*)(x + (size_t)c * LL + lbase + grp * 4));
    };

    unsigned long long acc[4][4];
#pragma unroll
    for (int op = 0; op < 4; op++)
#pragma unroll
        for (int p = 0; p < 4; p++) acc[op][p] = 0ull;

    LOAD(0);
    const int og = wid;
    for (int s = 0; s < NCHUNK; s++) {
        float ws0 = 0.f, ws1 = 0.f, ws2 = 0.f, ws3 = 0.f;
#pragma unroll
        for (int i = 0; i < 3; i++) {
            float lsv = __shfl_up_sync(0xffffffffu, d[i].w, 1);
            if (lane == 0) lsv = le[i];
            float rsv = __shfl_down_sync(0xffffffffu, a[i].x, 1);
            if (lane == 31) rsv = re[i];
            ws0 = fmaf(my[i], (a[i].y + b[i].x) + lsv, ws0);
            ws1 = fmaf(my[i], (a[i].z + b[i].y) + d[i].x, ws1);
            ws2 = fmaf(my[i], (a[i].w + b[i].z) + d[i].y, ws2);
            ws3 = fmaf(my[i], (rsv + b[i].w) + d[i].z, ws3);
        }
        float4 gv;
        gv.x = xv.x * ws0; gv.y = xv.y * ws1;
        gv.z = xv.z * ws2; gv.w = xv.w * ws3;
        *(float4*)(&sg[s & 1][cl * 128 + grp * 4]) = gv;
        if (s + 1 < NCHUNK) LOAD(s + 1);
        __syncthreads();
        const float* src = sg[s & 1];
#pragma unroll
        for (int c2 = 0; c2 < CHUNK; c2++) {
            const int c = s * CHUNK + c2;
            const float4 g4 = *(const float4*)(src + c2 * 128 + lane * 4);
            unsigned long long gp[4];
            asm("mov.b64 %0, {%1, %1};" : "=l"(gp[0]) : "f"(g4.x));
            asm("mov.b64 %0, {%1, %1};" : "=l"(gp[1]) : "f"(g4.y));
            asm("mov.b64 %0, {%1, %1};" : "=l"(gp[2]) : "f"(g4.z));
            asm("mov.b64 %0, {%1, %1};" : "=l"(gp[3]) : "f"(g4.w));
            const ulonglong2* cv = (const ulonglong2*)(sconv + c * CO + og * 8);
            const ulonglong2 cva = cv[0];
            const ulonglong2 cvb = cv[1];
#pragma unroll
            for (int p = 0; p < 4; p++) {
                asm("fma.rn.f32x2 %0, %1, %2, %0;" : "+l"(acc[0][p]) : "l"(cva.x), "l"(gp[p]));
                asm("fma.rn.f32x2 %0, %1, %2, %0;" : "+l"(acc[1][p]) : "l"(cva.y), "l"(gp[p]));
                asm("fma.rn.f32x2 %0, %1, %2, %0;" : "+l"(acc[2][p]) : "l"(cvb.x), "l"(gp[p]));
                asm("fma.rn.f32x2 %0, %1, %2, %0;" : "+l"(acc[3][p]) : "l"(cvb.y), "l"(gp[p]));
            }
        }
    }
#pragma unroll
    for (int op = 0; op < 4; op++) {
        unsigned int lo[4], hi[4];
#pragma unroll
        for (int p = 0; p < 4; p++) {
            asm("mov.b64 {%0, %1}, %2;" : "=r"(lo[p]), "=r"(hi[p]) : "l"(acc[op][p]));
        }
        const int o = og * 8 + 2 * op;
        float4 v0, v1;
        v0.x = __uint_as_float(lo[0]); v0.y = __uint_as_float(lo[1]);
        v0.z = __uint_as_float(lo[2]); v0.w = __uint_as_float(lo[3]);
        v1.x = __uint_as_float(hi[0]); v1.y = __uint_as_float(hi[1]);
        v1.z = __uint_as_float(hi[2]); v1.w = __uint_as_float(hi[3]);
        *(float4*)(out + (size_t)o * LL + lbase + lane * 4) = v0;
        *(float4*)(out + (size_t)(o + 1) * LL + lbase + lane * 4) = v1;
    }
}

// ===========================================================================
typedef CUresult (*EncodeFn)(CUtensorMap*, CUtensorMapDataType, cuuint32_t,
                             void*, const cuuint64_t*, const cuuint64_t*,
                             const cuuint32_t*, const cuuint32_t*,
                             CUtensorMapInterleave, CUtensorMapSwizzle,
                             CUtensorMapL2promotion, CUtensorMapFloatOOBfill);

extern "C" void kernel_launch(void* const* d_in, const int* in_sizes, int n_in,
                              void* d_out, int out_size) {
    const float* x    = (const float*)d_in[0];  // (1, C, S, S)
    const float* w    = (const float*)d_in[1];  // (1, C*9, L)
    const float* conv = (const float*)d_in[2];  // (C, CO)
    float* out = (float*)d_out;                 // (1, CO, S, S)

    EncodeFn enc = (EncodeFn)dlsym(RTLD_DEFAULT, "cuTensorMapEncodeTiled");

    bool tma_ok = false;
    CUtensorMap wmap, xmap;
    if (enc) {
        // w as 5D [x=256, y=256, j=3, i=3, c=64]
        cuuint64_t wd[5] = {256, 256, 3, 3, 64};
        cuuint64_t wst[4] = {1024ull, 262144ull, 786432ull, 2359296ull};
        cuuint32_t wbox[5] = {144, 1, 3, 1, 8};
        cuuint32_t wes[5] = {1, 1, 1, 1, 1};
        // x as 3D [x=256, y=256, c=64]
        cuuint64_t xd[3] = {256, 256, 64};
        cuuint64_t xst[2] = {1024ull, 262144ull};
        cuuint32_t xbox[3] = {128, 1, 8};
        cuuint32_t xes[3] = {1, 1, 1};
        CUresult r1 = enc(&wmap, CU_TENSOR_MAP_DATA_TYPE_FLOAT32, 5, (void*)w,
                          wd, wst, wbox, wes,
                          CU_TENSOR_MAP_INTERLEAVE_NONE, CU_TENSOR_MAP_SWIZZLE_NONE,
                          CU_TENSOR_MAP_L2_PROMOTION_L2_128B,
                          CU_TENSOR_MAP_FLOAT_OOB_FILL_NONE);
        CUresult r2 = enc(&xmap, CU_TENSOR_MAP_DATA_TYPE_FLOAT32, 3, (void*)x,
                          xd, xst, xbox, xes,
                          CU_TENSOR_MAP_INTERLEAVE_NONE, CU_TENSOR_MAP_SWIZZLE_NONE,
                          CU_TENSOR_MAP_L2_PROMOTION_L2_128B,
                          CU_TENSOR_MAP_FLOAT_OOB_FILL_NONE);
        tma_ok = (r1 == CUDA_SUCCESS) && (r2 == CUDA_SUCCESS);
    }

    if (tma_ok) {
        const int dyn = 2 * STAGE_B;   // 91136 B raw ring
        static bool attr_set = false;
        if (!attr_set) {
            cudaFuncSetAttribute(reverb_tma_kernel,
                                 cudaFuncAttributeMaxDynamicSharedMemorySize, dyn);
            attr_set = true;
        }
        reverb_tma_kernel<<<LL / 128, 256, dyn>>>(wmap, xmap, conv, out);
    } else {
        reverb_pipe_kernel<<<LL / 128, 256>>>(x, w, conv, out);
    }
}